// round 17
// baseline (speedup 1.0000x reference)
#include <cuda_runtime.h>
#include <cstdint>

#define B 8
#define T 4096
#define D 1024
#define S 64
#define BOND 32
#define NQ 8
#define QDIM 256
#define NCH 64         // chunks per batch (64 rows each)
#define NMID 80        // k_mid blocks (co-resident, gbar-safe)
#define NT 1024

// ------- device scratch (no allocations allowed) -------
__device__ float g_part[B * NCH * D];    // per-chunk column sums (2 MB)
__device__ float g_lp[64 * B * QDIM];    // per-kslice logit partials (512 KB)
__device__ float g_m0[B * 32];           // padded per batch
__device__ float g_m1[B * 32];
__device__ float g_overlaps[B * S];
__device__ float g_feats[S * NQ];
__device__ float g_fold[NQ * D];         // folded Wd
__device__ float g_bias[B * D];          // final per-batch bias rows
__device__ int   g_bar_count;            // zero-init
__device__ int   g_bar_gen;
__device__ int   g_done;                 // last-block counter (zero-init, self-reset)

// ---------------- software grid barrier (NMID blocks, all co-resident) ----------------
__device__ __forceinline__ void gbar() {
    __threadfence();
    __syncthreads();
    if (threadIdx.x == 0) {
        int gen = *(volatile int*)&g_bar_gen;
        if (atomicAdd(&g_bar_count, 1) == NMID - 1) {
            *(volatile int*)&g_bar_count = 0;
            __threadfence();
            *(volatile int*)&g_bar_gen = gen + 1;
        } else {
            while (*(volatile int*)&g_bar_gen == gen) __nanosleep(64);
        }
    }
    __syncthreads();
}

// ==== Kernel 1: per-chunk column sums (blocks 0..511) | fold Wd (blocks 512..543) ====
__global__ void k_partsum(const float* __restrict__ x, const float* __restrict__ Wd) {
    const int blk = blockIdx.x;
    const int tid = threadIdx.x;
    if (blk < 512) {
        const int c = blk & 63;
        const int b = blk >> 6;
        const float4* xp = reinterpret_cast<const float4*>(x) +
                           ((size_t)b * T + (size_t)c * 64) * 256 + tid;
        float4 acc = make_float4(0.f, 0.f, 0.f, 0.f);
#pragma unroll 8
        for (int r = 0; r < 64; ++r) {
            float4 v = xp[(size_t)r * 256];
            acc.x += v.x; acc.y += v.y; acc.z += v.z; acc.w += v.w;
        }
        reinterpret_cast<float4*>(g_part)[((size_t)b * NCH + c) * 256 + tid] = acc;
    } else {
        // fold[q][d] = sum_i Wd[i*8+q][d]; 32 blocks x 32 d's (overlaps with x stream)
        const int d = (blk - 512) * 32 + (tid >> 3);
        const int q = tid & 7;
        float acc = 0.f;
#pragma unroll 8
        for (int i = 0; i < 32; ++i)
            acc += Wd[(size_t)(i * 8 + q) * D + d];
        g_fold[q * D + d] = acc;
    }
}

// ============ Kernel 2: middle work, 80 x 1024, 2 gbars + last-block tail ============
__global__ void __launch_bounds__(NT, 1)
k_mid(const float* __restrict__ Wq,
      const float* __restrict__ bq,
      const float* __restrict__ bd,
      const float* __restrict__ cf,
      const float* __restrict__ cm,
      const float* __restrict__ cl) {
    __shared__ float smem[12288];   // 48 KB
    const int blk = blockIdx.x;
    const int tid = threadIdx.x;

    // ===== P1: GEMV partials for ALL batches (blocks 0..63) =====
    if (blk < 64) {
        float* pr = smem;            // 4 x 8 x 256 = 8192 floats (32 KB)
        float* xs_s = smem + 8192;   // 8 x 16 = 128 floats
        const int k0 = blk * 16;

        // self-gather xs slice: pair = (b, k'), 8 sub-threads each sum 8 c's
        {
            const int pair = tid >> 3;         // 0..127
            const int sub = tid & 7;
            const int b = pair >> 4;
            const int kk = pair & 15;
            float acc = 0.f;
#pragma unroll
            for (int m = 0; m < 8; ++m)
                acc += g_part[((size_t)b * NCH + (sub + 8 * m)) * D + k0 + kk];
#pragma unroll
            for (int o = 4; o; o >>= 1) acc += __shfl_xor_sync(0xffffffffu, acc, o);
            if (sub == 0) xs_s[b * 16 + kk] = acc * (1.0f / (float)T);
        }
        __syncthreads();

        // partial GEMV: thread (j, kc) covers 4 k's for all 8 batches
        const int j = tid & 255;
        const int kc = tid >> 8;
        {
            float acc[B];
#pragma unroll
            for (int b = 0; b < B; ++b) acc[b] = 0.f;
#pragma unroll
            for (int i = 0; i < 4; ++i) {
                const int kk = kc * 4 + i;
                const float wq = Wq[(size_t)(k0 + kk) * QDIM + j];
#pragma unroll
                for (int b = 0; b < B; ++b)
                    acc[b] = fmaf(xs_s[b * 16 + kk], wq, acc[b]);
            }
#pragma unroll
            for (int b = 0; b < B; ++b)
                pr[(kc * 8 + b) * 256 + j] = acc[b];
        }
        __syncthreads();

        // reduce over kc, store g_lp[blk][b][j]
#pragma unroll
        for (int h = 0; h < 2; ++h) {
            const int idx = tid + h * 1024;    // (b, j)
            const int b = idx >> 8;
            const int jj = idx & 255;
            float v = pr[(0 * 8 + b) * 256 + jj] + pr[(1 * 8 + b) * 256 + jj] +
                      pr[(2 * 8 + b) * 256 + jj] + pr[(3 * 8 + b) * 256 + jj];
            g_lp[((size_t)blk * B + b) * QDIM + jj] = v;
        }
    }
    gbar();

    // ===== P2: query finish (blocks 0..7) | cm preload + feats (blocks 16..79) =====
    if (blk < B) {
        float* pr2 = smem;           // 4 x 256
        float* qa = smem + 1024;     // 256
        float* red = smem + 1280;    // 8
        const int b = blk;
        const int j = tid & 255;
        const int pc = tid >> 8;
        {
            float acc = 0.f;
#pragma unroll
            for (int i = 0; i < 16; ++i) {
                const int p = pc * 16 + i;
                acc += g_lp[((size_t)p * B + b) * QDIM + j];
            }
            pr2[pc * 256 + j] = acc;
        }
        __syncthreads();

        float logit = 0.f;
        if (tid < QDIM)
            logit = (pr2[j] + pr2[256 + j]) + (pr2[512 + j] + pr2[768 + j]) + bq[j];

        // softmax over 256 — barriers uniform
        float m = logit;
#pragma unroll
        for (int o = 16; o; o >>= 1) m = fmaxf(m, __shfl_xor_sync(0xffffffffu, m, o));
        if (tid < QDIM && (tid & 31) == 0) red[tid >> 5] = m;
        __syncthreads();
        float bm = red[0];
#pragma unroll
        for (int i = 1; i < 8; ++i) bm = fmaxf(bm, red[i]);
        float e = (tid < QDIM) ? __expf(logit - bm) : 0.f;
        float ssum = e;
#pragma unroll
        for (int o = 16; o; o >>= 1) ssum += __shfl_xor_sync(0xffffffffu, ssum, o);
        __syncthreads();
        if (tid < QDIM && (tid & 31) == 0) red[tid >> 5] = ssum;
        __syncthreads();
        float tot = 0.f;
#pragma unroll
        for (int i = 0; i < 8; ++i) tot += red[i];
        if (tid < QDIM) qa[j] = e / tot;
        __syncthreads();

        if (tid < 16) {   // amplitude means, JAX OOB-clamp to index 255
            const int q = tid & 7;
            const bool one = tid >= 8;
            const int s = 1 << (7 - q);
            const int cin = min(s, 128 / s);
            float a = 0.f;
            const int off = one ? s : 0;
            for (int i = 0; i < cin; ++i) a += qa[i * 2 * s + off];
            a += (float)(s - cin) * qa[QDIM - 1];
            float* dst = one ? g_m1 : g_m0;
            dst[b * 32 + q] = a / (float)s;
        }
    } else if (blk >= 16) {
        // preload this slot's cm slice into smem + compute feats (query-independent)
        const int s = blk - 16;
        {
            const float4* src = reinterpret_cast<const float4*>(cm + (size_t)s * 12288);
            float4* dst = reinterpret_cast<float4*>(smem);
#pragma unroll
            for (int i = 0; i < 3; ++i)
                dst[i * 1024 + tid] = src[i * 1024 + tid];
        }
        __syncthreads();

        if (tid < 256) {
            const int w = tid >> 5;
            const int lane = tid & 31;
            float fsum, inv_cnt;
            if (w == 0) {
                fsum = cf[s * 64 + lane] + cf[s * 64 + 32 + lane];
                inv_cnt = 1.0f / 64.0f;
            } else if (w == 7) {
                fsum = cl[s * 64 + lane] + cl[s * 64 + 32 + lane];
                inv_cnt = 1.0f / 64.0f;
            } else {
                const float* base = smem + (w - 1) * 2048;
                fsum = 0.f;
#pragma unroll
                for (int i = 0; i < 64; ++i) fsum += base[i * 32 + lane];
                inv_cnt = 1.0f / 2048.0f;
            }
#pragma unroll
            for (int o = 16; o; o >>= 1) fsum += __shfl_xor_sync(0xffffffffu, fsum, o);
            if (lane == 0) g_feats[s * NQ + w] = fsum * inv_cnt;
        }
    }
    gbar();

    // ===== P3: slot overlaps (blocks 16..79; cm still in smem) =====
    if (blk >= 16) {
        const int s = blk - 16;
        if (tid < 256) {
            const int w = tid >> 5;
            const int lane = tid & 31;
            const int b = w;   // batch = warp
            float M0[NQ], M1[NQ];
#pragma unroll
            for (int q = 0; q < NQ; ++q) {
                M0[q] = __ldcg(&g_m0[b * 32 + q]);
                M1[q] = __ldcg(&g_m1[b * 32 + q]);
            }
            float v = M0[0] * cf[s * 64 + lane] + M1[0] * cf[s * 64 + 32 + lane];
#pragma unroll
            for (int q = 1; q <= NQ - 2; ++q) {
                const float* base = smem + (q - 1) * 2048;
                float nv = 0.f;
#pragma unroll 8
                for (int l = 0; l < BOND; ++l) {
                    float vl = __shfl_sync(0xffffffffu, v, l);
                    float c0 = base[l * 64 + lane];
                    float c1 = base[l * 64 + 32 + lane];
                    nv = fmaf(vl, fmaf(M0[q], c0, M1[q] * c1), nv);
                }
                v = nv;
            }
            float wl = M0[NQ - 1] * cl[(s * BOND + lane) * 2] +
                       M1[NQ - 1] * cl[(s * BOND + lane) * 2 + 1];
            float ov = v * wl;
#pragma unroll
            for (int o = 16; o; o >>= 1) ov += __shfl_xor_sync(0xffffffffu, ov, o);
            if (lane == 0) g_overlaps[b * S + s] = ov;
        }
    }

    // ===== P4 (last-block tail): attention + bias rows for ALL batches =====
    __threadfence();
    __syncthreads();
    __shared__ int s_last;
    if (tid == 0) s_last = (atomicAdd(&g_done, 1) == NMID - 1) ? 1 : 0;
    __syncthreads();
    if (s_last) {
        float* s_gg = smem + 10000;   // 64 floats (clear of slot cm region usage)

        if (tid < 256) {   // warp w = batch w
            const int w = tid >> 5;
            const int lane = tid & 31;
            float a0 = __ldcg(&g_overlaps[w * S + lane]);
            float a1 = __ldcg(&g_overlaps[w * S + 32 + lane]);
            float m = fmaxf(a0, a1);
#pragma unroll
            for (int o = 16; o; o >>= 1) m = fmaxf(m, __shfl_xor_sync(0xffffffffu, m, o));
            float e0 = __expf(a0 - m);
            float e1 = __expf(a1 - m);
            float ssum = e0 + e1;
#pragma unroll
            for (int o = 16; o; o >>= 1) ssum += __shfl_xor_sync(0xffffffffu, ssum, o);
            const float inv = 1.0f / ssum;
            const float at0 = e0 * inv;
            const float at1 = e1 * inv;
#pragma unroll
            for (int q = 0; q < NQ; ++q) {
                float p = at0 * __ldcg(&g_feats[lane * NQ + q]) +
                          at1 * __ldcg(&g_feats[(32 + lane) * NQ + q]);
#pragma unroll
                for (int o = 16; o; o >>= 1) p += __shfl_xor_sync(0xffffffffu, p, o);
                if (lane == 0) s_gg[w * NQ + q] = p;
            }
        }
        __syncthreads();

        {
            float f[NQ];
#pragma unroll
            for (int q = 0; q < NQ; ++q) f[q] = __ldcg(&g_fold[q * D + tid]);
            const float bdd = bd[tid];
#pragma unroll
            for (int b = 0; b < B; ++b) {
                float acc = bdd;
#pragma unroll
                for (int q = 0; q < NQ; ++q)
                    acc = fmaf(s_gg[b * NQ + q], f[q], acc);
                g_bias[b * D + tid] = acc;
            }
        }
        if (tid == 0) g_done = 0;   // reset for next graph replay
    }
}

// ==== Kernel 3: out = x + bias — reversed blocks, streaming stores ====
__global__ void k_add(const float* __restrict__ x, float* __restrict__ out) {
    const int rblk = (int)(gridDim.x - 1) - (int)blockIdx.x;   // reversed
    const int b = rblk >> 10;               // 1024 blocks per batch
    const size_t row0 = (size_t)rblk * 4;
    const int tid = threadIdx.x;
    const float4 bias = reinterpret_cast<const float4*>(g_bias)[b * (D / 4) + tid];
    const float4* xp = reinterpret_cast<const float4*>(x) + row0 * (D / 4);
    float4* op = reinterpret_cast<float4*>(out) + row0 * (D / 4);
#pragma unroll
    for (int r = 0; r < 4; ++r) {
        float4 v = xp[r * (D / 4) + tid];
        v.x += bias.x; v.y += bias.y; v.z += bias.z; v.w += bias.w;
        __stcs(&op[r * (D / 4) + tid], v);   // evict-first: keep x resident in L2
    }
}

extern "C" void kernel_launch(void* const* d_in, const int* in_sizes, int n_in,
                              void* d_out, int out_size) {
    const float* x  = (const float*)d_in[0];
    const float* Wq = (const float*)d_in[1];
    const float* bq = (const float*)d_in[2];
    const float* Wd = (const float*)d_in[3];
    const float* bd = (const float*)d_in[4];
    const float* cf = (const float*)d_in[5];
    const float* cm = (const float*)d_in[6];
    const float* cl = (const float*)d_in[7];
    float* out = (float*)d_out;

    k_partsum<<<544, 256>>>(x, Wd);
    k_mid<<<NMID, NT>>>(Wq, bq, bd, cf, cm, cl);
    k_add<<<(B * T) / 4, 256>>>(x, out);
}